// round 1
// baseline (speedup 1.0000x reference)
#include <cuda_runtime.h>
#include <math.h>

// -----------------------------------------------------------------------------
// NeuralSplineFourierFilter
//
// Stage 1 (setup, 1 block / 32 threads):
//   tiny MLP:  net1 = sin(a*W1+b1); net2 = sin(net1@W2+b2)
//   w    = net2@Ww+bw   (9)   -> control points c[10] = [0, w]
//   kraw = net2@Wk+bk   (7)   -> kpos[8] = [0, cumsum(softmax(kraw))]
//   knots ak[14] = [0,0,0, kpos(8), 1,1,1]
//   For each interval k in [3..9]: expand the cubic de Boor recursion
//   symbolically in u = xp - ak[k]  ->  4 monomial coefficients.
//   Writes a flat 48-float table to a __device__ global:
//     [0..5]   cmp values  = kpos[1..6]   (interval search thresholds)
//     [8..14]  t_k         = ak[3+i]
//     [16+4i..] coeffs a0,a1,a2,a3 per interval i (i = k-3)
//
// Stage 2 (eval, persistent grid-stride, float4 vectorized):
//   per element: xp = clamp(x/sqrt(3), 0, 0.9999)
//                k  = 6 compares; coeff = LDS.128; u = xp - t_k; Horner(3 FMA)
//   Pure HBM-bound streaming: 134 MB total traffic.
// -----------------------------------------------------------------------------

__device__ float g_tab[64];

__global__ void nsff_setup_kernel(const float* __restrict__ a,
                                  const float* __restrict__ W1,
                                  const float* __restrict__ b1,
                                  const float* __restrict__ W2,
                                  const float* __restrict__ b2,
                                  const float* __restrict__ Ww,
                                  const float* __restrict__ bw,
                                  const float* __restrict__ Wk,
                                  const float* __restrict__ bk) {
    __shared__ float net1[32];
    __shared__ float net2[32];
    __shared__ float sw[9];
    __shared__ float skraw[7];
    __shared__ float sak[14];
    __shared__ float sc[10];

    const int i = threadIdx.x;  // 32 threads

    // net1 = sin(a * W1 + b1)
    float av = a[0];
    net1[i] = sinf(av * W1[i] + b1[i]);
    __syncwarp();

    // net2 = sin(net1 @ W2 + b2)   (W2 is [32,32] row-major: W2[j*32 + i])
    {
        float acc = b2[i];
#pragma unroll
        for (int j = 0; j < 32; j++) acc += net1[j] * W2[j * 32 + i];
        net2[i] = sinf(acc);
    }
    __syncwarp();

    // w = net2 @ Ww + bw  (Ww is [32,9]);  kraw = net2 @ Wk + bk  (Wk is [32,7])
    if (i < 9) {
        float s = bw[i];
#pragma unroll
        for (int j = 0; j < 32; j++) s += net2[j] * Ww[j * 9 + i];
        sw[i] = s;
    }
    if (i < 7) {
        float s = bk[i];
#pragma unroll
        for (int j = 0; j < 32; j++) s += net2[j] * Wk[j * 7 + i];
        skraw[i] = s;
    }
    __syncwarp();

    // softmax + cumsum + knot vector (serial on lane 0; trivial cost)
    if (i == 0) {
        float m = skraw[0];
#pragma unroll
        for (int j = 1; j < 7; j++) m = fmaxf(m, skraw[j]);
        float e[7];
        float tot = 0.0f;
#pragma unroll
        for (int j = 0; j < 7; j++) { e[j] = expf(skraw[j] - m); tot += e[j]; }
        float inv = 1.0f / tot;

        sak[0] = sak[1] = sak[2] = 0.0f;
        sak[3] = 0.0f;                 // kpos[0]
        float cum = 0.0f;
#pragma unroll
        for (int j = 0; j < 7; j++) { cum += e[j] * inv; sak[4 + j] = cum; }
        sak[11] = sak[12] = sak[13] = 1.0f;

        sc[0] = 0.0f;
#pragma unroll
        for (int j = 0; j < 9; j++) sc[1 + j] = sw[j];

        // interval-search thresholds: kpos[1..6] = ak[4..9]
#pragma unroll
        for (int j = 0; j < 6; j++) g_tab[j] = sak[4 + j];
    }
    __syncwarp();

    // Per-interval cubic coefficient expansion: lanes 0..6 handle k = 3+lane.
    // Represent each de Boor stage d[j] as a cubic polynomial in u = xp - t_k.
    if (i < 7) {
        const int k = 3 + i;
        const float tk = sak[k];
        float P[4][4];
#pragma unroll
        for (int j = 0; j < 4; j++) {
            P[j][0] = sc[j + k - 3];
            P[j][1] = P[j][2] = P[j][3] = 0.0f;
        }
#pragma unroll
        for (int r = 1; r <= 3; r++) {
#pragma unroll
            for (int j = 3; j >= 1; j--) {
                if (j < r) continue;
                float ta = sak[j + k - 3];
                float tb = sak[j + 1 + k - r];
                float rcp = 1.0f / (tb - ta);
                float A = (tk - ta) * rcp;   // alpha = A + B*u
                float B = rcp;
                // newP[j] = (1 - A - B*u) * P[j-1] + (A + B*u) * P[j]
                float q0 = (1.0f - A) * P[j - 1][0] + A * P[j][0];
                float q1 = (1.0f - A) * P[j - 1][1] + A * P[j][1]
                         + B * (P[j][0] - P[j - 1][0]);
                float q2 = (1.0f - A) * P[j - 1][2] + A * P[j][2]
                         + B * (P[j][1] - P[j - 1][1]);
                float q3 = (1.0f - A) * P[j - 1][3] + A * P[j][3]
                         + B * (P[j][2] - P[j - 1][2]);
                P[j][0] = q0; P[j][1] = q1; P[j][2] = q2; P[j][3] = q3;
            }
        }
        g_tab[8 + i]  = tk;
        g_tab[16 + 4 * i + 0] = P[3][0];
        g_tab[16 + 4 * i + 1] = P[3][1];
        g_tab[16 + 4 * i + 2] = P[3][2];
        g_tab[16 + 4 * i + 3] = P[3][3];
    }
}

// 1/sqrt(3) to fp64 accuracy, rounded to fp32
#define NSFF_RSQRT3 0.57735026918962576f
#define NSFF_XMAX   0.9999f   // fp32(1.0 - 0.0001)

__device__ __forceinline__ float nsff_eval_one(
    float xx,
    float c0, float c1, float c2, float c3, float c4, float c5,
    const float* __restrict__ s_tab) {
    float xp = fminf(fmaxf(xx * NSFF_RSQRT3, 0.0f), NSFF_XMAX);
    int k = (xp >= c0) + (xp >= c1) + (xp >= c2)
          + (xp >= c3) + (xp >= c4) + (xp >= c5);
    const float4 cf = *reinterpret_cast<const float4*>(&s_tab[16 + 4 * k]);
    float u = xp - s_tab[8 + k];
    return fmaf(fmaf(fmaf(cf.w, u, cf.z), u, cf.y), u, cf.x);
}

__global__ void __launch_bounds__(256)
nsff_eval_kernel(const float* __restrict__ x, float* __restrict__ out, int n4) {
    __shared__ __align__(16) float s_tab[64];
    if (threadIdx.x < 48) s_tab[threadIdx.x] = g_tab[threadIdx.x];
    __syncthreads();

    // hoist interval thresholds into registers (uniform across block)
    const float c0 = s_tab[0], c1 = s_tab[1], c2 = s_tab[2];
    const float c3 = s_tab[3], c4 = s_tab[4], c5 = s_tab[5];

    const float4* __restrict__ x4 = reinterpret_cast<const float4*>(x);
    float4* __restrict__ o4 = reinterpret_cast<float4*>(out);

    int idx = blockIdx.x * blockDim.x + threadIdx.x;
    const int stride = gridDim.x * blockDim.x;
    for (; idx < n4; idx += stride) {
        float4 v = x4[idx];
        float4 r;
        r.x = nsff_eval_one(v.x, c0, c1, c2, c3, c4, c5, s_tab);
        r.y = nsff_eval_one(v.y, c0, c1, c2, c3, c4, c5, s_tab);
        r.z = nsff_eval_one(v.z, c0, c1, c2, c3, c4, c5, s_tab);
        r.w = nsff_eval_one(v.w, c0, c1, c2, c3, c4, c5, s_tab);
        o4[idx] = r;
    }
}

extern "C" void kernel_launch(void* const* d_in, const int* in_sizes, int n_in,
                              void* d_out, int out_size) {
    const float* x  = (const float*)d_in[0];
    const float* a  = (const float*)d_in[1];
    const float* W1 = (const float*)d_in[2];
    const float* b1 = (const float*)d_in[3];
    const float* W2 = (const float*)d_in[4];
    const float* b2 = (const float*)d_in[5];
    const float* Ww = (const float*)d_in[6];
    const float* bw = (const float*)d_in[7];
    const float* Wk = (const float*)d_in[8];
    const float* bk = (const float*)d_in[9];
    float* out = (float*)d_out;

    nsff_setup_kernel<<<1, 32>>>(a, W1, b1, W2, b2, Ww, bw, Wk, bk);

    const int n = out_size;          // 256^3 = 16,777,216 (divisible by 4)
    const int n4 = n / 4;
    int blocks = 152 * 8;            // persistent-ish: ~64 warps/SM
    int need = (n4 + 255) / 256;
    if (blocks > need) blocks = need;
    nsff_eval_kernel<<<blocks, 256>>>(x, out, n4);
}